// round 16
// baseline (speedup 1.0000x reference)
#include <cuda_runtime.h>
#include <math.h>

// Problem constants
#define BG   64
#define NPG  512
#define DEG  32
#define EPG  (NPG*DEG)      // 16384 edges per graph
#define NE   (BG*EPG)       // 1048576
#define NN   (BG*NPG)       // 32768

// packed fp32x2 FMA: d = a*b + d (componentwise)
#define FMA2(d, a, b) asm("fma.rn.f32x2 %0, %1, %2, %0;" : "+l"(d) : "l"(a), "l"(b))
#define UNPK(lo, hi, v) asm("mov.b64 {%0,%1}, %2;" : "=f"(lo), "=f"(hi) : "l"(v))

// ---------------- device scratch (no runtime alloc allowed) ----------------
__device__ int   g_srcs[NE];       // src node per edge, sorted by dst
__device__ float g_eas[NE*8];      // ea reordered to sorted edge positions (32 MB)
__device__ int   g_off[NN];
__device__ int   g_cnt[NN];
__device__ float g_pre[NN*64];     // pre1
__device__ float g_preB[NN*64];    // pre2
__device__ float g_R[NN*64];       // edge-phase accumulator
__device__ float g_h2[NN*64];
__device__ float g_pre3[NN*16];
__device__ float g_s[NN*16];
// pre-splatted weights: [k][2f] with each value duplicated
__device__ float g_w2s1[64*128];   // g1w2 splat
__device__ float g_wns1[64*128];   // g2w1[0:64] splat
__device__ float g_w2s2[64*128];   // g2w2 splat
__device__ float g_wns2[64*32];    // agw1[0:64] (64x16) splat

// ------ CSR build: counting sort by dst; scatters src + ea into sorted order ------
__global__ void build_csr_k(const int* __restrict__ src, const int* __restrict__ dst,
                            const float* __restrict__ ea) {
    __shared__ int scnt[NPG];
    __shared__ int wsum[16];
    int g = blockIdx.x, t = threadIdx.x;
    scnt[t] = 0;
    __syncthreads();
    int ebase = g * EPG, nbase = g * NPG;
    for (int e = t; e < EPG; e += NPG)
        atomicAdd(&scnt[dst[ebase + e] - nbase], 1);
    __syncthreads();
    int lane = t & 31, w = t >> 5;
    int v = scnt[t];
    int incl = v;
    #pragma unroll
    for (int d = 1; d < 32; d <<= 1) {
        int u = __shfl_up_sync(0xffffffffu, incl, d);
        if (lane >= d) incl += u;
    }
    if (lane == 31) wsum[w] = incl;
    __syncthreads();
    if (t == 0) {
        int run = 0;
        #pragma unroll
        for (int i = 0; i < 16; i++) { int x = wsum[i]; wsum[i] = run; run += x; }
    }
    __syncthreads();
    int excl = incl - v + wsum[w];
    g_off[nbase + t] = ebase + excl;
    g_cnt[nbase + t] = v;
    __syncthreads();
    scnt[t] = excl;                 // reuse as scatter cursor
    __syncthreads();
    for (int e = t; e < EPG; e += NPG) {
        int ge = ebase + e;
        int sv = src[ge];
        int d = dst[ge] - nbase;
        int p = atomicAdd(&scnt[d], 1);
        int gp = ebase + p;
        g_srcs[gp] = sv;
        const float4* ein = (const float4*)(ea + (size_t)ge * 8);
        float4* eout = (float4*)(g_eas + (size_t)gp * 8);
        eout[0] = __ldg(ein);
        eout[1] = __ldg(ein + 1);
    }
}

// ------ one-shot weight splat: out[k][2f]={w[k][f],w[k][f]} for the 4 GEMM weights ----
__global__ void presplat_k(const float* __restrict__ w2a, const float* __restrict__ wna,
                           const float* __restrict__ w2b, const float* __restrict__ wnb) {
    int i = blockIdx.x * blockDim.x + threadIdx.x;
    if (i < 64 * 64) {
        float v = __ldg(w2a + i);
        g_w2s1[2 * i] = v; g_w2s1[2 * i + 1] = v;
        v = __ldg(wna + i);
        g_wns1[2 * i] = v; g_wns1[2 * i + 1] = v;
        v = __ldg(w2b + i);
        g_w2s2[2 * i] = v; g_w2s2[2 * i + 1] = v;
    }
    if (i < 64 * 16) {
        float v = __ldg(wnb + i);
        g_wns2[2 * i] = v; g_wns2[2 * i + 1] = v;
    }
}

// ---------------- pre1 = x @ g1_w1[0:16] + g1_b1 ----------------
__global__ void pre1_k(const float* __restrict__ x, const float* __restrict__ w,
                       const float* __restrict__ b, float* __restrict__ out) {
    int t = threadIdx.x, warp = t >> 5, lane = t & 31;
    int c0 = 2 * lane, c1 = c0 + 1;
    float wc0[16], wc1[16];
    #pragma unroll
    for (int k = 0; k < 16; k++) { wc0[k] = __ldg(w + k * 64 + c0); wc1[k] = __ldg(w + k * 64 + c1); }
    float b0 = __ldg(b + c0), b1 = __ldg(b + c1);
    int nbase = (blockIdx.x * 8 + warp) * 8;
    for (int m = 0; m < 8; m++) {
        int n = nbase + m;
        const float4* row = (const float4*)(x + (size_t)n * 16);
        float4 r0 = __ldg(row + 0), r1 = __ldg(row + 1), r2 = __ldg(row + 2), r3 = __ldg(row + 3);
        float rv[16] = {r0.x, r0.y, r0.z, r0.w, r1.x, r1.y, r1.z, r1.w,
                        r2.x, r2.y, r2.z, r2.w, r3.x, r3.y, r3.z, r3.w};
        float d0 = b0, d1 = b1;
        #pragma unroll
        for (int k = 0; k < 16; k++) { d0 = fmaf(rv[k], wc0[k], d0); d1 = fmaf(rv[k], wc1[k], d1); }
        ((float2*)out)[(size_t)n * 32 + lane] = make_float2(d0, d1);
    }
}

// 8 fused FMAs of one edge's ea-vector against hoisted weight regs
#define EDGE_FMA(E0, E1, A0, A1)                                        \
    E0 = fmaf(A0.x, we0[0], E0); E1 = fmaf(A0.x, we1[0], E1);           \
    E0 = fmaf(A0.y, we0[1], E0); E1 = fmaf(A0.y, we1[1], E1);           \
    E0 = fmaf(A0.z, we0[2], E0); E1 = fmaf(A0.z, we1[2], E1);           \
    E0 = fmaf(A0.w, we0[3], E0); E1 = fmaf(A0.w, we1[3], E1);           \
    E0 = fmaf(A1.x, we0[4], E0); E1 = fmaf(A1.x, we1[4], E1);           \
    E0 = fmaf(A1.y, we0[5], E0); E1 = fmaf(A1.y, we1[5], E1);           \
    E0 = fmaf(A1.z, we0[6], E0); E1 = fmaf(A1.z, we1[6], E1);           \
    E0 = fmaf(A1.w, we0[7], E0); E1 = fmaf(A1.w, we1[7], E1);

// ---- edge-only aggregation: R[n] = sum_{e in(n)} relu(pre[src_e] + ea_e @ w1e) ----
// warp per node, 4-edge unroll (R5 structure) on SORTED arrays (linear ea).
__global__ void __launch_bounds__(256) edge_k(const float* __restrict__ pre,
                                              const float* __restrict__ w1e,
                                              float* __restrict__ Rout) {
    int t = threadIdx.x, warp = t >> 5, lane = t & 31;
    float we0[8], we1[8];
    #pragma unroll
    for (int k = 0; k < 8; k++) {
        float2 wv = __ldg((const float2*)(w1e + k * 64) + lane);
        we0[k] = wv.x; we1[k] = wv.y;
    }
    int n = blockIdx.x * 8 + warp;
    int off = g_off[n], cnt = g_cnt[n];
    const int* ss = g_srcs + off;
    const float4* eab = (const float4*)g_eas + (size_t)off * 2;
    float accA0 = 0.f, accA1 = 0.f, accB0 = 0.f, accB1 = 0.f;
    int j = 0;
    for (; j + 4 <= cnt; j += 4) {
        int s0 = __ldg(ss + j);
        int s1 = __ldg(ss + j + 1);
        int s2 = __ldg(ss + j + 2);
        int s3 = __ldg(ss + j + 3);
        float4 a00 = __ldg(eab + 2 * j),     a01 = __ldg(eab + 2 * j + 1);
        float4 a10 = __ldg(eab + 2 * j + 2), a11 = __ldg(eab + 2 * j + 3);
        float4 a20 = __ldg(eab + 2 * j + 4), a21 = __ldg(eab + 2 * j + 5);
        float4 a30 = __ldg(eab + 2 * j + 6), a31 = __ldg(eab + 2 * j + 7);
        float2 g0 = __ldg((const float2*)(pre + (size_t)s0 * 64) + lane);
        float2 g1 = __ldg((const float2*)(pre + (size_t)s1 * 64) + lane);
        float2 g2 = __ldg((const float2*)(pre + (size_t)s2 * 64) + lane);
        float2 g3 = __ldg((const float2*)(pre + (size_t)s3 * 64) + lane);
        float e00 = g0.x, e01 = g0.y, e10 = g1.x, e11 = g1.y;
        float e20 = g2.x, e21 = g2.y, e30 = g3.x, e31 = g3.y;
        EDGE_FMA(e00, e01, a00, a01)
        EDGE_FMA(e10, e11, a10, a11)
        EDGE_FMA(e20, e21, a20, a21)
        EDGE_FMA(e30, e31, a30, a31)
        accA0 += fmaxf(e00, 0.f); accA1 += fmaxf(e01, 0.f);
        accB0 += fmaxf(e10, 0.f); accB1 += fmaxf(e11, 0.f);
        accA0 += fmaxf(e20, 0.f); accA1 += fmaxf(e21, 0.f);
        accB0 += fmaxf(e30, 0.f); accB1 += fmaxf(e31, 0.f);
    }
    for (; j < cnt; j++) {
        int s0 = __ldg(ss + j);
        float4 a00 = __ldg(eab + 2 * j), a01 = __ldg(eab + 2 * j + 1);
        float2 g0 = __ldg((const float2*)(pre + (size_t)s0 * 64) + lane);
        float e00 = g0.x, e01 = g0.y;
        EDGE_FMA(e00, e01, a00, a01)
        accA0 += fmaxf(e00, 0.f); accA1 += fmaxf(e01, 0.f);
    }
    ((float2*)Rout)[(size_t)n * 32 + lane] = make_float2(accA0 + accB0, accA1 + accB1);
}

// ---- batched epilogue GEMM: 64 nodes/CTA (grid 512), R5 compute structure,
//      weights pre-splatted in gmem -> staging is a straight float4 copy.
template<int FN, bool WRITE_H>
__global__ void __launch_bounds__(256) gemm_k(
    const float* __restrict__ R, const float* __restrict__ w2s, const float* __restrict__ b2,
    const float* __restrict__ wns, const float* __restrict__ bn,
    float* __restrict__ outh, float* __restrict__ outp) {
    __shared__ __align__(16) float sA[64 * 68];    // R^T then h^T: [k][node], pad 68
    __shared__ __align__(16) float sWS[64 * 128];  // splatted weights [k][2f] (reused)
    __shared__ float sb2[64];
    __shared__ float sbn[FN];
    __shared__ float scnt[64];
    int t = threadIdx.x;
    int node0 = blockIdx.x * 64;
    for (int i = t; i < 64 * 16; i += 256) {
        float4 v = __ldg((const float4*)(R + (size_t)node0 * 64) + i);
        int n = i >> 4, k4 = (i & 15) * 4;
        sA[(k4 + 0) * 68 + n] = v.x; sA[(k4 + 1) * 68 + n] = v.y;
        sA[(k4 + 2) * 68 + n] = v.z; sA[(k4 + 3) * 68 + n] = v.w;
    }
    for (int i = t; i < 64 * 32; i += 256)
        ((float4*)sWS)[i] = __ldg((const float4*)w2s + i);
    if (t < 64) { sb2[t] = b2[t]; scnt[t] = (float)g_cnt[node0 + t]; }
    if (t < FN) sbn[t] = bn[t];
    __syncthreads();

    int tx = t & 15, ty = t >> 4;
    int f0 = tx * 4, m0 = ty * 4;
    unsigned long long c[8];
    #pragma unroll
    for (int i = 0; i < 8; i++) c[i] = 0ull;
    #pragma unroll 4
    for (int k = 0; k < 64; k++) {
        ulonglong2 a = *(const ulonglong2*)(sA + k * 68 + m0);
        ulonglong2 b01 = *(const ulonglong2*)(sWS + k * 128 + 2 * f0);
        ulonglong2 b23 = *(const ulonglong2*)(sWS + k * 128 + 2 * f0 + 4);
        FMA2(c[0], a.x, b01.x); FMA2(c[1], a.x, b01.y);
        FMA2(c[2], a.x, b23.x); FMA2(c[3], a.x, b23.y);
        FMA2(c[4], a.y, b01.x); FMA2(c[5], a.y, b01.y);
        FMA2(c[6], a.y, b23.x); FMA2(c[7], a.y, b23.y);
    }
    float hv[4][4];
    #pragma unroll
    for (int p = 0; p < 2; p++) {
        float cA = scnt[m0 + 2 * p], cB = scnt[m0 + 2 * p + 1];
        float iA = 1.f / fmaxf(cA, 1.f), iB = 1.f / fmaxf(cB, 1.f);
        #pragma unroll
        for (int jj = 0; jj < 4; jj++) {
            float lo, hi; UNPK(lo, hi, c[p * 4 + jj]);
            float bf = sb2[f0 + jj];
            hv[2 * p][jj]     = fmaxf((lo + cA * bf) * iA, 0.f);
            hv[2 * p + 1][jj] = fmaxf((hi + cB * bf) * iB, 0.f);
        }
    }
    if (WRITE_H) {
        #pragma unroll
        for (int m = 0; m < 4; m++)
            *(float4*)(outh + (size_t)(node0 + m0 + m) * 64 + f0) =
                make_float4(hv[m][0], hv[m][1], hv[m][2], hv[m][3]);
    }
    __syncthreads();
    #pragma unroll
    for (int p = 0; p < 2; p++)
        #pragma unroll
        for (int jj = 0; jj < 4; jj++)
            *(float2*)(sA + (f0 + jj) * 68 + m0 + 2 * p) =
                make_float2(hv[2 * p][jj], hv[2 * p + 1][jj]);
    for (int i = t; i < 64 * FN / 2; i += 256)
        ((float4*)sWS)[i] = __ldg((const float4*)wns + i);
    __syncthreads();
    if (FN == 64 || tx < 4) {
        #pragma unroll
        for (int i = 0; i < 8; i++) c[i] = 0ull;
        #pragma unroll 4
        for (int k = 0; k < 64; k++) {
            ulonglong2 a = *(const ulonglong2*)(sA + k * 68 + m0);
            ulonglong2 b01 = *(const ulonglong2*)(sWS + k * (2 * FN) + 2 * f0);
            ulonglong2 b23 = *(const ulonglong2*)(sWS + k * (2 * FN) + 2 * f0 + 4);
            FMA2(c[0], a.x, b01.x); FMA2(c[1], a.x, b01.y);
            FMA2(c[2], a.x, b23.x); FMA2(c[3], a.x, b23.y);
            FMA2(c[4], a.y, b01.x); FMA2(c[5], a.y, b01.y);
            FMA2(c[6], a.y, b23.x); FMA2(c[7], a.y, b23.y);
        }
        #pragma unroll
        for (int p = 0; p < 2; p++) {
            float pe[4], po[4];
            #pragma unroll
            for (int jj = 0; jj < 4; jj++) {
                float lo, hi; UNPK(lo, hi, c[p * 4 + jj]);
                pe[jj] = lo + sbn[f0 + jj]; po[jj] = hi + sbn[f0 + jj];
            }
            *(float4*)(outp + (size_t)(node0 + m0 + 2 * p) * FN + f0) =
                make_float4(pe[0], pe[1], pe[2], pe[3]);
            *(float4*)(outp + (size_t)(node0 + m0 + 2 * p + 1) * FN + f0) =
                make_float4(po[0], po[1], po[2], po[3]);
        }
    }
}

// ------- assign conv (F=16) + fused double softmax; half-warp per edge, 2-unrolled ----
__global__ void agg3_k(const float* __restrict__ pre,
                       const float* __restrict__ w1e, const float* __restrict__ w2,
                       const float* __restrict__ b2, float* __restrict__ s_out) {
    __shared__ float sw2[256];
    __shared__ float sb2[16];
    __shared__ float rbuf[8][16];
    int t = threadIdx.x;
    if (t < 256) sw2[t] = w2[t];
    if (t < 16)  sb2[t] = b2[t];
    int warp = t >> 5, lane = t & 31, half = lane >> 4, f = lane & 15;
    float we[8];
    #pragma unroll
    for (int k = 0; k < 8; k++) we[k] = __ldg(w1e + k * 16 + f);
    __syncthreads();

    int n = blockIdx.x * 8 + warp;
    int off = g_off[n], cnt = g_cnt[n];
    const int* ss = g_srcs + off;
    const float4* eab = (const float4*)g_eas + (size_t)off * 2;
    float acc0 = 0.f, acc1 = 0.f;
    int j = half;
    for (; j + 2 < cnt; j += 4) {
        int s0 = __ldg(ss + j);
        int s1 = __ldg(ss + j + 2);
        float4 a00 = __ldg(eab + 2 * j), a01 = __ldg(eab + 2 * j + 1);
        float4 a10 = __ldg(eab + 2 * j + 4), a11 = __ldg(eab + 2 * j + 5);
        float e0 = __ldg(pre + (size_t)s0 * 16 + f);
        float e1 = __ldg(pre + (size_t)s1 * 16 + f);
        e0 = fmaf(a00.x, we[0], e0); e0 = fmaf(a00.y, we[1], e0);
        e0 = fmaf(a00.z, we[2], e0); e0 = fmaf(a00.w, we[3], e0);
        e0 = fmaf(a01.x, we[4], e0); e0 = fmaf(a01.y, we[5], e0);
        e0 = fmaf(a01.z, we[6], e0); e0 = fmaf(a01.w, we[7], e0);
        e1 = fmaf(a10.x, we[0], e1); e1 = fmaf(a10.y, we[1], e1);
        e1 = fmaf(a10.z, we[2], e1); e1 = fmaf(a10.w, we[3], e1);
        e1 = fmaf(a11.x, we[4], e1); e1 = fmaf(a11.y, we[5], e1);
        e1 = fmaf(a11.z, we[6], e1); e1 = fmaf(a11.w, we[7], e1);
        acc0 += fmaxf(e0, 0.f);
        acc1 += fmaxf(e1, 0.f);
    }
    for (; j < cnt; j += 2) {
        int s0 = __ldg(ss + j);
        float4 a00 = __ldg(eab + 2 * j), a01 = __ldg(eab + 2 * j + 1);
        float e0 = __ldg(pre + (size_t)s0 * 16 + f);
        e0 = fmaf(a00.x, we[0], e0); e0 = fmaf(a00.y, we[1], e0);
        e0 = fmaf(a00.z, we[2], e0); e0 = fmaf(a00.w, we[3], e0);
        e0 = fmaf(a01.x, we[4], e0); e0 = fmaf(a01.y, we[5], e0);
        e0 = fmaf(a01.z, we[6], e0); e0 = fmaf(a01.w, we[7], e0);
        acc0 += fmaxf(e0, 0.f);
    }
    float acc = acc0 + acc1;
    acc += __shfl_xor_sync(0xffffffffu, acc, 16);
    if (half == 0) rbuf[warp][f] = acc;
    __syncwarp();
    float cntf = (float)cnt;
    float inv = 1.f / fmaxf(cntf, 1.f);
    float d = cntf * sb2[f];
    #pragma unroll
    for (int k = 0; k < 16; k++) d = fmaf(rbuf[warp][k], sw2[k * 16 + f], d);
    d *= inv;
    // double softmax over the 16-lane group (reference softmaxes twice)
    #pragma unroll
    for (int pass = 0; pass < 2; pass++) {
        float m = d;
        #pragma unroll
        for (int msk = 8; msk; msk >>= 1) m = fmaxf(m, __shfl_xor_sync(0xffffffffu, m, msk));
        float e = __expf(d - m);
        float ssum = e;
        #pragma unroll
        for (int msk = 8; msk; msk >>= 1) ssum += __shfl_xor_sync(0xffffffffu, ssum, msk);
        d = e / ssum;
    }
    if (half == 0) s_out[(size_t)n * 16 + f] = d;
}

// ---------------- fused pooling + dense head: one CTA per graph ----------------
__global__ void __launch_bounds__(256) pool_k(
    const float* __restrict__ s, const float* __restrict__ h,
    const float* __restrict__ d1w, const float* __restrict__ d1b,
    const float* __restrict__ d2w, const float* __restrict__ d2b,
    const float* __restrict__ mw1, const float* __restrict__ mb1,
    const float* __restrict__ mw2, const float* __restrict__ mb2,
    float* __restrict__ out) {
    __shared__ float ss[NPG * 16];          // 32 KB
    __shared__ float sT[NPG * 16];          // 32 KB: T, then x1 partials [8][1024]
    __shared__ float adj[256], an[256], dvv[16];
    __shared__ float x1s[1024], tb[1024];
    __shared__ float gv[64], hidb[128], red2[128];
    int g = blockIdx.x, t = threadIdx.x;    // 256 threads
    int warp = t >> 5, lane = t & 31;

    for (int i = t; i < NPG * 16; i += 256) ss[i] = s[(size_t)g * NPG * 16 + i];
    __syncthreads();

    // T phase: warp handles 64 dst nodes; lanes split 16 features x 2 edge halves
    {
        int f = lane & 15, half = lane >> 4;
        for (int dn = warp * 64; dn < warp * 64 + 64; dn++) {
            int node = g * NPG + dn;
            int off = g_off[node], cnt = g_cnt[node];
            const int* sp = g_srcs + off;
            float acc = 0.f;
            for (int j = half; j < cnt; j += 2) {
                int sv = __ldg(sp + j);
                acc += ss[(sv & (NPG - 1)) * 16 + f];
            }
            acc += __shfl_xor_sync(0xffffffffu, acc, 16);
            if (half == 0) sT[dn * 16 + f] = acc;
        }
    }
    __syncthreads();
    // adj[c][k] = sum_d T[d][c] * s[d][k]
    {
        int c = t >> 4, k = t & 15;
        float a = 0.f;
        for (int d = 0; d < NPG; d++)
            a = fmaf(sT[d * 16 + c], ss[d * 16 + k], a);
        adj[t] = a;
    }
    __syncthreads();
    // x1 partials: warp handles 64 nodes; lane holds feature pair (2*lane, 2*lane+1)
    {
        float2 acc[16];
        #pragma unroll
        for (int i = 0; i < 16; i++) acc[i] = make_float2(0.f, 0.f);
        for (int dn = warp * 64; dn < warp * 64 + 64; dn++) {
            float2 hv = __ldg((const float2*)(h + ((size_t)g * NPG + dn) * 64) + lane);
            #pragma unroll
            for (int cc = 0; cc < 16; cc++) {
                float sv = ss[dn * 16 + cc];
                acc[cc].x = fmaf(sv, hv.x, acc[cc].x);
                acc[cc].y = fmaf(sv, hv.y, acc[cc].y);
            }
        }
        #pragma unroll
        for (int cc = 0; cc < 16; cc++) {
            sT[warp * 1024 + cc * 64 + 2 * lane]     = acc[cc].x;
            sT[warp * 1024 + cc * 64 + 2 * lane + 1] = acc[cc].y;
        }
    }
    __syncthreads();
    for (int i = t; i < 1024; i += 256) {
        float a = 0.f;
        #pragma unroll
        for (int w = 0; w < 8; w++) a += sT[w * 1024 + i];
        x1s[i] = a;
    }
    __syncthreads();
    // dense GCN head
    if (t < 16) adj[t * 16 + t] = 1.f;
    __syncthreads();
    if (t < 16) {
        float sd = 0.f;
        for (int k = 0; k < 16; k++) sd += adj[t * 16 + k];
        dvv[t] = rsqrtf(fmaxf(sd, 1.f));
    }
    __syncthreads();
    an[t] = dvv[t >> 4] * adj[t] * dvv[t & 15];
    __syncthreads();
    // layer 1
    for (int i = t; i < 1024; i += 256) {
        int cc = i >> 6, f = i & 63;
        float acc = 0.f;
        for (int m = 0; m < 64; m++) acc = fmaf(x1s[cc * 64 + m], __ldg(d1w + m * 64 + f), acc);
        tb[i] = acc;
    }
    __syncthreads();
    for (int i = t; i < 1024; i += 256) {
        int cc = i >> 6, f = i & 63;
        float acc = __ldg(d1b + f);
        for (int k = 0; k < 16; k++) acc = fmaf(an[cc * 16 + k], tb[k * 64 + f], acc);
        x1s[i] = fmaxf(acc, 0.f);
    }
    __syncthreads();
    // layer 2
    for (int i = t; i < 1024; i += 256) {
        int cc = i >> 6, f = i & 63;
        float acc = 0.f;
        for (int m = 0; m < 64; m++) acc = fmaf(x1s[cc * 64 + m], __ldg(d2w + m * 64 + f), acc);
        tb[i] = acc;
    }
    __syncthreads();
    for (int i = t; i < 1024; i += 256) {
        int cc = i >> 6, f = i & 63;
        float acc = __ldg(d2b + f);
        for (int k = 0; k < 16; k++) acc = fmaf(an[cc * 16 + k], tb[k * 64 + f], acc);
        x1s[i] = fmaxf(acc, 0.f);
    }
    __syncthreads();
    // final pool: softmax over size-1 axis == ones => plain sum over clusters
    if (t < 64) {
        float sd = 0.f;
        for (int cc = 0; cc < 16; cc++) sd += x1s[cc * 64 + t];
        gv[t] = sd;
    }
    __syncthreads();
    if (t < 128) {
        float acc = __ldg(mb1 + t);
        for (int f = 0; f < 64; f++) acc = fmaf(gv[f], __ldg(mw1 + f * 128 + t), acc);
        hidb[t] = fmaxf(acc, 0.f);
    }
    __syncthreads();
    if (t < 128) red2[t] = hidb[t] * __ldg(mw2 + t);
    __syncthreads();
    for (int sdx = 64; sdx > 0; sdx >>= 1) {
        if (t < sdx) red2[t] += red2[t + sdx];
        __syncthreads();
    }
    if (t == 0) out[g] = red2[0] + __ldg(mb2);
}

// ---------------- host ----------------
template<typename T>
static T* sym_addr(const void* sym) {
    void* p = nullptr;
    cudaGetSymbolAddress(&p, sym);
    return (T*)p;
}

extern "C" void kernel_launch(void* const* d_in, const int* in_sizes, int n_in,
                              void* d_out, int out_size) {
    const float* x    = (const float*)d_in[0];
    const int*   ei   = (const int*)d_in[1];
    const float* ea   = (const float*)d_in[2];
    const float* g1w1 = (const float*)d_in[4];
    const float* g1b1 = (const float*)d_in[5];
    const float* g1w2 = (const float*)d_in[6];
    const float* g1b2 = (const float*)d_in[7];
    const float* g2w1 = (const float*)d_in[8];
    const float* g2b1 = (const float*)d_in[9];
    const float* g2w2 = (const float*)d_in[10];
    const float* g2b2 = (const float*)d_in[11];
    const float* agw1 = (const float*)d_in[12];
    const float* agb1 = (const float*)d_in[13];
    const float* agw2 = (const float*)d_in[14];
    const float* agb2 = (const float*)d_in[15];
    const float* d1w  = (const float*)d_in[16];
    const float* d1b  = (const float*)d_in[17];
    const float* d2w  = (const float*)d_in[18];
    const float* d2b  = (const float*)d_in[19];
    // d_in[20..21] = ad_w, ad_b (dead: softmax over size-1 axis => ones)
    const float* mw1  = (const float*)d_in[22];
    const float* mb1  = (const float*)d_in[23];
    const float* mw2  = (const float*)d_in[24];
    const float* mb2  = (const float*)d_in[25];
    float* out = (float*)d_out;

    const int* src = ei;
    const int* dst = ei + NE;

    float* pre  = sym_addr<float>(g_pre);
    float* preB = sym_addr<float>(g_preB);
    float* R    = sym_addr<float>(g_R);
    float* h2   = sym_addr<float>(g_h2);
    float* pre3 = sym_addr<float>(g_pre3);
    float* s    = sym_addr<float>(g_s);
    float* w2s1 = sym_addr<float>(g_w2s1);
    float* wns1 = sym_addr<float>(g_wns1);
    float* w2s2 = sym_addr<float>(g_w2s2);
    float* wns2 = sym_addr<float>(g_wns2);

    build_csr_k<<<BG, NPG>>>(src, dst, ea);
    presplat_k<<<16, 256>>>(g1w2, g2w1, g2w2, agw1);

    // conv1
    pre1_k<<<NN / 64, 256>>>(x, g1w1, g1b1, pre);
    edge_k<<<NN / 8, 256>>>(pre, g1w1 + 16 * 64, R);
    gemm_k<64, false><<<NN / 64, 256>>>(R, w2s1, g1b2, wns1, g2b1, nullptr, preB);

    // conv2 (writes h2 + fused assign node-pre 64->16)
    edge_k<<<NN / 8, 256>>>(preB, g2w1 + 64 * 64, R);
    gemm_k<16, true><<<NN / 64, 256>>>(R, w2s2, g2b2, wns2, agb1, h2, pre3);

    // assign conv (16 feats) + fused double softmax
    agg3_k<<<NN / 8, 256>>>(pre3, agw1 + 64 * 16, agw2, agb2, s);

    // fused pooling + dense head -> output [64]
    pool_k<<<BG, 256>>>(s, h2, d1w, d1b, d2w, d2b, mw1, mb1, mw2, mb2, out);
}

// round 17
// speedup vs baseline: 1.5413x; 1.5413x over previous
#include <cuda_runtime.h>
#include <math.h>

// Problem constants
#define BG   64
#define NPG  512
#define DEG  32
#define EPG  (NPG*DEG)      // 16384 edges per graph
#define NE   (BG*EPG)       // 1048576
#define NN   (BG*NPG)       // 32768

// packed fp32x2 FMA: d = a*b + d (componentwise)
#define FMA2(d, a, b) asm("fma.rn.f32x2 %0, %1, %2, %0;" : "+l"(d) : "l"(a), "l"(b))
#define UNPK(lo, hi, v) asm("mov.b64 {%0,%1}, %2;" : "=f"(lo), "=f"(hi) : "l"(v))

// ---------------- device scratch (no runtime alloc allowed) ----------------
__device__ int2  g_perm2[NE];      // (edge index, src node) sorted by dst
__device__ int   g_off[NN];
__device__ int   g_cnt[NN];
__device__ float g_pre[NN*64];     // pre1
__device__ float g_preB[NN*64];    // pre2
__device__ float g_R[NN*64];       // edge-phase accumulator
__device__ float g_h2[NN*64];
__device__ float g_pre3[NN*16];
__device__ float g_s[NN*16];
// pre-splatted weights: [k][2f] with each value duplicated
__device__ float g_w2s1[64*128];   // g1w2 splat
__device__ float g_wns1[64*128];   // g2w1[0:64] splat
__device__ float g_w2s2[64*128];   // g2w2 splat
__device__ float g_wns2[64*32];    // agw1[0:64] (64x16) splat

// ---------------- CSR build: counting sort by dst, parallel scan ----------------
__global__ void build_csr_k(const int* __restrict__ src, const int* __restrict__ dst) {
    __shared__ int scnt[NPG];
    __shared__ int wsum[16];
    int g = blockIdx.x, t = threadIdx.x;
    scnt[t] = 0;
    __syncthreads();
    int ebase = g * EPG, nbase = g * NPG;
    for (int e = t; e < EPG; e += NPG)
        atomicAdd(&scnt[dst[ebase + e] - nbase], 1);
    __syncthreads();
    int lane = t & 31, w = t >> 5;
    int v = scnt[t];
    int incl = v;
    #pragma unroll
    for (int d = 1; d < 32; d <<= 1) {
        int u = __shfl_up_sync(0xffffffffu, incl, d);
        if (lane >= d) incl += u;
    }
    if (lane == 31) wsum[w] = incl;
    __syncthreads();
    if (t == 0) {
        int run = 0;
        #pragma unroll
        for (int i = 0; i < 16; i++) { int x = wsum[i]; wsum[i] = run; run += x; }
    }
    __syncthreads();
    int excl = incl - v + wsum[w];
    g_off[nbase + t] = ebase + excl;
    g_cnt[nbase + t] = v;
    __syncthreads();
    scnt[t] = excl;                 // reuse as scatter cursor
    __syncthreads();
    for (int e = t; e < EPG; e += NPG) {
        int sv = src[ebase + e];
        int d = dst[ebase + e] - nbase;
        int p = atomicAdd(&scnt[d], 1);
        g_perm2[ebase + p] = make_int2(ebase + e, sv);
    }
}

// ------ one-shot weight splat: out[k][2f]={w[k][f],w[k][f]} for the 4 GEMM weights ----
__global__ void presplat_k(const float* __restrict__ w2a, const float* __restrict__ wna,
                           const float* __restrict__ w2b, const float* __restrict__ wnb) {
    int i = blockIdx.x * blockDim.x + threadIdx.x;
    if (i < 64 * 64) {
        float v = __ldg(w2a + i);
        g_w2s1[2 * i] = v; g_w2s1[2 * i + 1] = v;
        v = __ldg(wna + i);
        g_wns1[2 * i] = v; g_wns1[2 * i + 1] = v;
        v = __ldg(w2b + i);
        g_w2s2[2 * i] = v; g_w2s2[2 * i + 1] = v;
    }
    if (i < 64 * 16) {
        float v = __ldg(wnb + i);
        g_wns2[2 * i] = v; g_wns2[2 * i + 1] = v;
    }
}

// ---------------- pre1 = x @ g1_w1[0:16] + g1_b1 ----------------
__global__ void pre1_k(const float* __restrict__ x, const float* __restrict__ w,
                       const float* __restrict__ b, float* __restrict__ out) {
    int t = threadIdx.x, warp = t >> 5, lane = t & 31;
    int c0 = 2 * lane, c1 = c0 + 1;
    float wc0[16], wc1[16];
    #pragma unroll
    for (int k = 0; k < 16; k++) { wc0[k] = __ldg(w + k * 64 + c0); wc1[k] = __ldg(w + k * 64 + c1); }
    float b0 = __ldg(b + c0), b1 = __ldg(b + c1);
    int nbase = (blockIdx.x * 8 + warp) * 8;
    for (int m = 0; m < 8; m++) {
        int n = nbase + m;
        const float4* row = (const float4*)(x + (size_t)n * 16);
        float4 r0 = __ldg(row + 0), r1 = __ldg(row + 1), r2 = __ldg(row + 2), r3 = __ldg(row + 3);
        float rv[16] = {r0.x, r0.y, r0.z, r0.w, r1.x, r1.y, r1.z, r1.w,
                        r2.x, r2.y, r2.z, r2.w, r3.x, r3.y, r3.z, r3.w};
        float d0 = b0, d1 = b1;
        #pragma unroll
        for (int k = 0; k < 16; k++) { d0 = fmaf(rv[k], wc0[k], d0); d1 = fmaf(rv[k], wc1[k], d1); }
        ((float2*)out)[(size_t)n * 32 + lane] = make_float2(d0, d1);
    }
}

// 8 fused FMAs of one edge's ea-vector against hoisted weight regs
#define EDGE_FMA(E0, E1, A0, A1)                                        \
    E0 = fmaf(A0.x, we0[0], E0); E1 = fmaf(A0.x, we1[0], E1);           \
    E0 = fmaf(A0.y, we0[1], E0); E1 = fmaf(A0.y, we1[1], E1);           \
    E0 = fmaf(A0.z, we0[2], E0); E1 = fmaf(A0.z, we1[2], E1);           \
    E0 = fmaf(A0.w, we0[3], E0); E1 = fmaf(A0.w, we1[3], E1);           \
    E0 = fmaf(A1.x, we0[4], E0); E1 = fmaf(A1.x, we1[4], E1);           \
    E0 = fmaf(A1.y, we0[5], E0); E1 = fmaf(A1.y, we1[5], E1);           \
    E0 = fmaf(A1.z, we0[6], E0); E1 = fmaf(A1.z, we1[6], E1);           \
    E0 = fmaf(A1.w, we0[7], E0); E1 = fmaf(A1.w, we1[7], E1);

// ---- edge-only aggregation: R[n] = sum_{e in(n)} relu(pre[src_e] + ea_e @ w1e) ----
// 4-edge unroll: all loads for 4 edges issued before any consumption (MLP ~16).
__global__ void __launch_bounds__(256) edge_k(const float* __restrict__ ea,
                                              const float* __restrict__ pre,
                                              const float* __restrict__ w1e,
                                              float* __restrict__ Rout) {
    int t = threadIdx.x, warp = t >> 5, lane = t & 31;
    float we0[8], we1[8];
    #pragma unroll
    for (int k = 0; k < 8; k++) {
        float2 wv = __ldg((const float2*)(w1e + k * 64) + lane);
        we0[k] = wv.x; we1[k] = wv.y;
    }
    int n = blockIdx.x * 8 + warp;
    int off = g_off[n], cnt = g_cnt[n];
    const int2* pp = g_perm2 + off;
    float accA0 = 0.f, accA1 = 0.f, accB0 = 0.f, accB1 = 0.f;
    int j = 0;
    for (; j + 4 <= cnt; j += 4) {
        int2 p0 = __ldg(pp + j);
        int2 p1 = __ldg(pp + j + 1);
        int2 p2 = __ldg(pp + j + 2);
        int2 p3 = __ldg(pp + j + 3);
        const float4* q0 = (const float4*)(ea + (size_t)p0.x * 8);
        const float4* q1 = (const float4*)(ea + (size_t)p1.x * 8);
        const float4* q2 = (const float4*)(ea + (size_t)p2.x * 8);
        const float4* q3 = (const float4*)(ea + (size_t)p3.x * 8);
        float4 a00 = __ldg(q0), a01 = __ldg(q0 + 1);
        float4 a10 = __ldg(q1), a11 = __ldg(q1 + 1);
        float4 a20 = __ldg(q2), a21 = __ldg(q2 + 1);
        float4 a30 = __ldg(q3), a31 = __ldg(q3 + 1);
        float2 g0 = __ldg((const float2*)(pre + (size_t)p0.y * 64) + lane);
        float2 g1 = __ldg((const float2*)(pre + (size_t)p1.y * 64) + lane);
        float2 g2 = __ldg((const float2*)(pre + (size_t)p2.y * 64) + lane);
        float2 g3 = __ldg((const float2*)(pre + (size_t)p3.y * 64) + lane);
        float e00 = g0.x, e01 = g0.y, e10 = g1.x, e11 = g1.y;
        float e20 = g2.x, e21 = g2.y, e30 = g3.x, e31 = g3.y;
        EDGE_FMA(e00, e01, a00, a01)
        EDGE_FMA(e10, e11, a10, a11)
        EDGE_FMA(e20, e21, a20, a21)
        EDGE_FMA(e30, e31, a30, a31)
        accA0 += fmaxf(e00, 0.f); accA1 += fmaxf(e01, 0.f);
        accB0 += fmaxf(e10, 0.f); accB1 += fmaxf(e11, 0.f);
        accA0 += fmaxf(e20, 0.f); accA1 += fmaxf(e21, 0.f);
        accB0 += fmaxf(e30, 0.f); accB1 += fmaxf(e31, 0.f);
    }
    for (; j < cnt; j++) {
        int2 p0 = __ldg(pp + j);
        const float4* q0 = (const float4*)(ea + (size_t)p0.x * 8);
        float4 a00 = __ldg(q0), a01 = __ldg(q0 + 1);
        float2 g0 = __ldg((const float2*)(pre + (size_t)p0.y * 64) + lane);
        float e00 = g0.x, e01 = g0.y;
        EDGE_FMA(e00, e01, a00, a01)
        accA0 += fmaxf(e00, 0.f); accA1 += fmaxf(e01, 0.f);
    }
    ((float2*)Rout)[(size_t)n * 32 + lane] = make_float2(accA0 + accB0, accA1 + accB1);
}

// ---- batched epilogue GEMM: 64 nodes/CTA (grid 512), R5 compute structure,
//      weights pre-splatted in gmem -> staging is a straight float4 copy.
template<int FN, bool WRITE_H>
__global__ void __launch_bounds__(256) gemm_k(
    const float* __restrict__ R, const float* __restrict__ w2s, const float* __restrict__ b2,
    const float* __restrict__ wns, const float* __restrict__ bn,
    float* __restrict__ outh, float* __restrict__ outp) {
    __shared__ __align__(16) float sA[64 * 68];    // R^T then h^T: [k][node], pad 68
    __shared__ __align__(16) float sWS[64 * 128];  // splatted weights [k][2f] (reused)
    __shared__ float sb2[64];
    __shared__ float sbn[FN];
    __shared__ float scnt[64];
    int t = threadIdx.x;
    int node0 = blockIdx.x * 64;
    for (int i = t; i < 64 * 16; i += 256) {
        float4 v = __ldg((const float4*)(R + (size_t)node0 * 64) + i);
        int n = i >> 4, k4 = (i & 15) * 4;
        sA[(k4 + 0) * 68 + n] = v.x; sA[(k4 + 1) * 68 + n] = v.y;
        sA[(k4 + 2) * 68 + n] = v.z; sA[(k4 + 3) * 68 + n] = v.w;
    }
    for (int i = t; i < 64 * 32; i += 256)
        ((float4*)sWS)[i] = __ldg((const float4*)w2s + i);
    if (t < 64) { sb2[t] = b2[t]; scnt[t] = (float)g_cnt[node0 + t]; }
    if (t < FN) sbn[t] = bn[t];
    __syncthreads();

    int tx = t & 15, ty = t >> 4;
    int f0 = tx * 4, m0 = ty * 4;
    unsigned long long c[8];
    #pragma unroll
    for (int i = 0; i < 8; i++) c[i] = 0ull;
    #pragma unroll 4
    for (int k = 0; k < 64; k++) {
        ulonglong2 a = *(const ulonglong2*)(sA + k * 68 + m0);
        ulonglong2 b01 = *(const ulonglong2*)(sWS + k * 128 + 2 * f0);
        ulonglong2 b23 = *(const ulonglong2*)(sWS + k * 128 + 2 * f0 + 4);
        FMA2(c[0], a.x, b01.x); FMA2(c[1], a.x, b01.y);
        FMA2(c[2], a.x, b23.x); FMA2(c[3], a.x, b23.y);
        FMA2(c[4], a.y, b01.x); FMA2(c[5], a.y, b01.y);
        FMA2(c[6], a.y, b23.x); FMA2(c[7], a.y, b23.y);
    }
    float hv[4][4];
    #pragma unroll
    for (int p = 0; p < 2; p++) {
        float cA = scnt[m0 + 2 * p], cB = scnt[m0 + 2 * p + 1];
        float iA = 1.f / fmaxf(cA, 1.f), iB = 1.f / fmaxf(cB, 1.f);
        #pragma unroll
        for (int jj = 0; jj < 4; jj++) {
            float lo, hi; UNPK(lo, hi, c[p * 4 + jj]);
            float bf = sb2[f0 + jj];
            hv[2 * p][jj]     = fmaxf((lo + cA * bf) * iA, 0.f);
            hv[2 * p + 1][jj] = fmaxf((hi + cB * bf) * iB, 0.f);
        }
    }
    if (WRITE_H) {
        #pragma unroll
        for (int m = 0; m < 4; m++)
            *(float4*)(outh + (size_t)(node0 + m0 + m) * 64 + f0) =
                make_float4(hv[m][0], hv[m][1], hv[m][2], hv[m][3]);
    }
    __syncthreads();
    #pragma unroll
    for (int p = 0; p < 2; p++)
        #pragma unroll
        for (int jj = 0; jj < 4; jj++)
            *(float2*)(sA + (f0 + jj) * 68 + m0 + 2 * p) =
                make_float2(hv[2 * p][jj], hv[2 * p + 1][jj]);
    for (int i = t; i < 64 * FN / 2; i += 256)
        ((float4*)sWS)[i] = __ldg((const float4*)wns + i);
    __syncthreads();
    if (FN == 64 || tx < 4) {
        #pragma unroll
        for (int i = 0; i < 8; i++) c[i] = 0ull;
        #pragma unroll 4
        for (int k = 0; k < 64; k++) {
            ulonglong2 a = *(const ulonglong2*)(sA + k * 68 + m0);
            ulonglong2 b01 = *(const ulonglong2*)(sWS + k * (2 * FN) + 2 * f0);
            ulonglong2 b23 = *(const ulonglong2*)(sWS + k * (2 * FN) + 2 * f0 + 4);
            FMA2(c[0], a.x, b01.x); FMA2(c[1], a.x, b01.y);
            FMA2(c[2], a.x, b23.x); FMA2(c[3], a.x, b23.y);
            FMA2(c[4], a.y, b01.x); FMA2(c[5], a.y, b01.y);
            FMA2(c[6], a.y, b23.x); FMA2(c[7], a.y, b23.y);
        }
        #pragma unroll
        for (int p = 0; p < 2; p++) {
            float pe[4], po[4];
            #pragma unroll
            for (int jj = 0; jj < 4; jj++) {
                float lo, hi; UNPK(lo, hi, c[p * 4 + jj]);
                pe[jj] = lo + sbn[f0 + jj]; po[jj] = hi + sbn[f0 + jj];
            }
            *(float4*)(outp + (size_t)(node0 + m0 + 2 * p) * FN + f0) =
                make_float4(pe[0], pe[1], pe[2], pe[3]);
            *(float4*)(outp + (size_t)(node0 + m0 + 2 * p + 1) * FN + f0) =
                make_float4(po[0], po[1], po[2], po[3]);
        }
    }
}

// ------- assign conv (F=16) + fused double softmax; half-warp per edge, 2-unrolled ----
__global__ void agg3_k(const float* __restrict__ ea, const float* __restrict__ pre,
                       const float* __restrict__ w1e, const float* __restrict__ w2,
                       const float* __restrict__ b2, float* __restrict__ s_out) {
    __shared__ float sw2[256];
    __shared__ float sb2[16];
    __shared__ float rbuf[8][16];
    int t = threadIdx.x;
    if (t < 256) sw2[t] = w2[t];
    if (t < 16)  sb2[t] = b2[t];
    int warp = t >> 5, lane = t & 31, half = lane >> 4, f = lane & 15;
    float we[8];
    #pragma unroll
    for (int k = 0; k < 8; k++) we[k] = __ldg(w1e + k * 16 + f);
    __syncthreads();

    int n = blockIdx.x * 8 + warp;
    int off = g_off[n], cnt = g_cnt[n];
    const int2* pp = g_perm2 + off;
    float acc0 = 0.f, acc1 = 0.f;
    int j = half;
    for (; j + 2 < cnt; j += 4) {
        int2 p0 = __ldg(pp + j);
        int2 p1 = __ldg(pp + j + 2);
        const float4* q0 = (const float4*)(ea + (size_t)p0.x * 8);
        const float4* q1 = (const float4*)(ea + (size_t)p1.x * 8);
        float4 a00 = __ldg(q0), a01 = __ldg(q0 + 1);
        float4 a10 = __ldg(q1), a11 = __ldg(q1 + 1);
        float e0 = __ldg(pre + (size_t)p0.y * 16 + f);
        float e1 = __ldg(pre + (size_t)p1.y * 16 + f);
        e0 = fmaf(a00.x, we[0], e0); e0 = fmaf(a00.y, we[1], e0);
        e0 = fmaf(a00.z, we[2], e0); e0 = fmaf(a00.w, we[3], e0);
        e0 = fmaf(a01.x, we[4], e0); e0 = fmaf(a01.y, we[5], e0);
        e0 = fmaf(a01.z, we[6], e0); e0 = fmaf(a01.w, we[7], e0);
        e1 = fmaf(a10.x, we[0], e1); e1 = fmaf(a10.y, we[1], e1);
        e1 = fmaf(a10.z, we[2], e1); e1 = fmaf(a10.w, we[3], e1);
        e1 = fmaf(a11.x, we[4], e1); e1 = fmaf(a11.y, we[5], e1);
        e1 = fmaf(a11.z, we[6], e1); e1 = fmaf(a11.w, we[7], e1);
        acc0 += fmaxf(e0, 0.f);
        acc1 += fmaxf(e1, 0.f);
    }
    for (; j < cnt; j += 2) {
        int2 p0 = __ldg(pp + j);
        const float4* q0 = (const float4*)(ea + (size_t)p0.x * 8);
        float4 a00 = __ldg(q0), a01 = __ldg(q0 + 1);
        float e0 = __ldg(pre + (size_t)p0.y * 16 + f);
        e0 = fmaf(a00.x, we[0], e0); e0 = fmaf(a00.y, we[1], e0);
        e0 = fmaf(a00.z, we[2], e0); e0 = fmaf(a00.w, we[3], e0);
        e0 = fmaf(a01.x, we[4], e0); e0 = fmaf(a01.y, we[5], e0);
        e0 = fmaf(a01.z, we[6], e0); e0 = fmaf(a01.w, we[7], e0);
        acc0 += fmaxf(e0, 0.f);
    }
    float acc = acc0 + acc1;
    acc += __shfl_xor_sync(0xffffffffu, acc, 16);
    if (half == 0) rbuf[warp][f] = acc;
    __syncwarp();
    float cntf = (float)cnt;
    float inv = 1.f / fmaxf(cntf, 1.f);
    float d = cntf * sb2[f];
    #pragma unroll
    for (int k = 0; k < 16; k++) d = fmaf(rbuf[warp][k], sw2[k * 16 + f], d);
    d *= inv;
    // double softmax over the 16-lane group (reference softmaxes twice)
    #pragma unroll
    for (int pass = 0; pass < 2; pass++) {
        float m = d;
        #pragma unroll
        for (int msk = 8; msk; msk >>= 1) m = fmaxf(m, __shfl_xor_sync(0xffffffffu, m, msk));
        float e = __expf(d - m);
        float ssum = e;
        #pragma unroll
        for (int msk = 8; msk; msk >>= 1) ssum += __shfl_xor_sync(0xffffffffu, ssum, msk);
        d = e / ssum;
    }
    if (half == 0) s_out[(size_t)n * 16 + f] = d;
}

// ---------------- fused pooling + dense head: one CTA per graph ----------------
__global__ void __launch_bounds__(256) pool_k(
    const float* __restrict__ s, const float* __restrict__ h,
    const float* __restrict__ d1w, const float* __restrict__ d1b,
    const float* __restrict__ d2w, const float* __restrict__ d2b,
    const float* __restrict__ mw1, const float* __restrict__ mb1,
    const float* __restrict__ mw2, const float* __restrict__ mb2,
    float* __restrict__ out) {
    __shared__ float ss[NPG * 16];          // 32 KB
    __shared__ float sT[NPG * 16];          // 32 KB: T, then x1 partials [8][1024]
    __shared__ float adj[256], an[256], dvv[16];
    __shared__ float x1s[1024], tb[1024];
    __shared__ float gv[64], hidb[128], red2[128];
    int g = blockIdx.x, t = threadIdx.x;    // 256 threads
    int warp = t >> 5, lane = t & 31;

    for (int i = t; i < NPG * 16; i += 256) ss[i] = s[(size_t)g * NPG * 16 + i];
    __syncthreads();

    // T phase: warp handles 64 dst nodes; lanes split 16 features x 2 edge halves
    {
        int f = lane & 15, half = lane >> 4;
        for (int dn = warp * 64; dn < warp * 64 + 64; dn++) {
            int node = g * NPG + dn;
            int off = g_off[node], cnt = g_cnt[node];
            const int2* pp = g_perm2 + off;
            float acc = 0.f;
            for (int j = half; j < cnt; j += 2) {
                int2 p = __ldg(pp + j);
                acc += ss[(p.y & (NPG - 1)) * 16 + f];
            }
            acc += __shfl_xor_sync(0xffffffffu, acc, 16);
            if (half == 0) sT[dn * 16 + f] = acc;
        }
    }
    __syncthreads();
    // adj[c][k] = sum_d T[d][c] * s[d][k]
    {
        int c = t >> 4, k = t & 15;
        float a = 0.f;
        for (int d = 0; d < NPG; d++)
            a = fmaf(sT[d * 16 + c], ss[d * 16 + k], a);
        adj[t] = a;
    }
    __syncthreads();
    // x1 partials: warp handles 64 nodes; lane holds feature pair (2*lane, 2*lane+1)
    {
        float2 acc[16];
        #pragma unroll
        for (int i = 0; i < 16; i++) acc[i] = make_float2(0.f, 0.f);
        for (int dn = warp * 64; dn < warp * 64 + 64; dn++) {
            float2 hv = __ldg((const float2*)(h + ((size_t)g * NPG + dn) * 64) + lane);
            #pragma unroll
            for (int cc = 0; cc < 16; cc++) {
                float sv = ss[dn * 16 + cc];
                acc[cc].x = fmaf(sv, hv.x, acc[cc].x);
                acc[cc].y = fmaf(sv, hv.y, acc[cc].y);
            }
        }
        #pragma unroll
        for (int cc = 0; cc < 16; cc++) {
            sT[warp * 1024 + cc * 64 + 2 * lane]     = acc[cc].x;
            sT[warp * 1024 + cc * 64 + 2 * lane + 1] = acc[cc].y;
        }
    }
    __syncthreads();
    for (int i = t; i < 1024; i += 256) {
        float a = 0.f;
        #pragma unroll
        for (int w = 0; w < 8; w++) a += sT[w * 1024 + i];
        x1s[i] = a;
    }
    __syncthreads();
    // dense GCN head
    if (t < 16) adj[t * 16 + t] = 1.f;
    __syncthreads();
    if (t < 16) {
        float sd = 0.f;
        for (int k = 0; k < 16; k++) sd += adj[t * 16 + k];
        dvv[t] = rsqrtf(fmaxf(sd, 1.f));
    }
    __syncthreads();
    an[t] = dvv[t >> 4] * adj[t] * dvv[t & 15];
    __syncthreads();
    // layer 1
    for (int i = t; i < 1024; i += 256) {
        int cc = i >> 6, f = i & 63;
        float acc = 0.f;
        for (int m = 0; m < 64; m++) acc = fmaf(x1s[cc * 64 + m], __ldg(d1w + m * 64 + f), acc);
        tb[i] = acc;
    }
    __syncthreads();
    for (int i = t; i < 1024; i += 256) {
        int cc = i >> 6, f = i & 63;
        float acc = __ldg(d1b + f);
        for (int k = 0; k < 16; k++) acc = fmaf(an[cc * 16 + k], tb[k * 64 + f], acc);
        x1s[i] = fmaxf(acc, 0.f);
    }
    __syncthreads();
    // layer 2
    for (int i = t; i < 1024; i += 256) {
        int cc = i >> 6, f = i & 63;
        float acc = 0.f;
        for (int m = 0; m < 64; m++) acc = fmaf(x1s[cc * 64 + m], __ldg(d2w + m * 64 + f), acc);
        tb[i] = acc;
    }
    __syncthreads();
    for (int i = t; i < 1024; i += 256) {
        int cc = i >> 6, f = i & 63;
        float acc = __ldg(d2b + f);
        for (int k = 0; k < 16; k++) acc = fmaf(an[cc * 16 + k], tb[k * 64 + f], acc);
        x1s[i] = fmaxf(acc, 0.f);
    }
    __syncthreads();
    // final pool: softmax over size-1 axis == ones => plain sum over clusters
    if (t < 64) {
        float sd = 0.f;
        for (int cc = 0; cc < 16; cc++) sd += x1s[cc * 64 + t];
        gv[t] = sd;
    }
    __syncthreads();
    if (t < 128) {
        float acc = __ldg(mb1 + t);
        for (int f = 0; f < 64; f++) acc = fmaf(gv[f], __ldg(mw1 + f * 128 + t), acc);
        hidb[t] = fmaxf(acc, 0.f);
    }
    __syncthreads();
    if (t < 128) red2[t] = hidb[t] * __ldg(mw2 + t);
    __syncthreads();
    for (int sdx = 64; sdx > 0; sdx >>= 1) {
        if (t < sdx) red2[t] += red2[t + sdx];
        __syncthreads();
    }
    if (t == 0) out[g] = red2[0] + __ldg(mb2);
}

// ---------------- host ----------------
template<typename T>
static T* sym_addr(const void* sym) {
    void* p = nullptr;
    cudaGetSymbolAddress(&p, sym);
    return (T*)p;
}

extern "C" void kernel_launch(void* const* d_in, const int* in_sizes, int n_in,
                              void* d_out, int out_size) {
    const float* x    = (const float*)d_in[0];
    const int*   ei   = (const int*)d_in[1];
    const float* ea   = (const float*)d_in[2];
    const float* g1w1 = (const float*)d_in[4];
    const float* g1b1 = (const float*)d_in[5];
    const float* g1w2 = (const float*)d_in[6];
    const float* g1b2 = (const float*)d_in[7];
    const float* g2w1 = (const float*)d_in[8];
    const float* g2b1 = (const float*)d_in[9];
    const float* g2w2 = (const float*)d_in[10];
    const float* g2b2 = (const float*)d_in[11];
    const float* agw1 = (const float*)d_in[12];
    const float* agb1 = (const float*)d_in[13];
    const float* agw2 = (const float*)d_in[14];
    const float* agb2 = (const float*)d_in[15];
    const float* d1w  = (const float*)d_in[16];
    const float* d1b  = (const float*)d_in[17];
    const float* d2w  = (const float*)d_in[18];
    const float* d2b  = (const float*)d_in[19];
    // d_in[20..21] = ad_w, ad_b (dead: softmax over size-1 axis => ones)
    const float* mw1  = (const float*)d_in[22];
    const float* mb1  = (const float*)d_in[23];
    const float* mw2  = (const float*)d_in[24];
    const float* mb2  = (const float*)d_in[25];
    float* out = (float*)d_out;

    const int* src = ei;
    const int* dst = ei + NE;

    float* pre  = sym_addr<float>(g_pre);
    float* preB = sym_addr<float>(g_preB);
    float* R    = sym_addr<float>(g_R);
    float* h2   = sym_addr<float>(g_h2);
    float* pre3 = sym_addr<float>(g_pre3);
    float* s    = sym_addr<float>(g_s);
    float* w2s1 = sym_addr<float>(g_w2s1);
    float* wns1 = sym_addr<float>(g_wns1);
    float* w2s2 = sym_addr<float>(g_w2s2);
    float* wns2 = sym_addr<float>(g_wns2);

    build_csr_k<<<BG, NPG>>>(src, dst);
    presplat_k<<<16, 256>>>(g1w2, g2w1, g2w2, agw1);

    // conv1
    pre1_k<<<NN / 64, 256>>>(x, g1w1, g1b1, pre);
    edge_k<<<NN / 8, 256>>>(ea, pre, g1w1 + 16 * 64, R);
    gemm_k<64, false><<<NN / 64, 256>>>(R, w2s1, g1b2, wns1, g2b1, nullptr, preB);

    // conv2 (writes h2 + fused assign node-pre 64->16)
    edge_k<<<NN / 8, 256>>>(ea, preB, g2w1 + 64 * 64, R);
    gemm_k<16, true><<<NN / 64, 256>>>(R, w2s2, g2b2, wns2, agb1, h2, pre3);

    // assign conv (16 feats) + fused double softmax
    agg3_k<<<NN / 8, 256>>>(ea, pre3, agw1 + 64 * 16, agw2, agb2, s);

    // fused pooling + dense head -> output [64]
    pool_k<<<BG, 256>>>(s, h2, d1w, d1b, d2w, d2b, mw1, mb1, mw2, mb2, out);
}